// round 1
// baseline (speedup 1.0000x reference)
#include <cuda_runtime.h>
#include <math.h>

#define EPS 1e-8f

__device__ __forceinline__ float warp_sum(float v) {
    #pragma unroll
    for (int o = 16; o > 0; o >>= 1)
        v += __shfl_xor_sync(0xFFFFFFFFu, v, o);
    return v;
}

__global__ void __launch_bounds__(256) hybrid_rbf_kernel(
    const float* __restrict__ x,
    const float* __restrict__ y,
    float* __restrict__ out,
    int B)
{
    const int gtid = blockIdx.x * blockDim.x + threadIdx.x;
    const int row  = gtid >> 5;
    const int lane = gtid & 31;
    if (row >= B) return;

    const float2* xr = reinterpret_cast<const float2*>(x + (size_t)row * 64);
    const float2* yr = reinterpret_cast<const float2*>(y + (size_t)row * 64);
    const float2 xv = xr[lane];
    const float2 yv = yr[lane];

    // ---- Pass 1: row statistics (sum, sum of squares) for x and y ----
    float sx  = xv.x + xv.y;
    float sy  = yv.x + yv.y;
    float sxx = xv.x * xv.x + xv.y * xv.y;
    float syy = yv.x * yv.x + yv.y * yv.y;

    #pragma unroll
    for (int o = 16; o > 0; o >>= 1) {
        sx  += __shfl_xor_sync(0xFFFFFFFFu, sx,  o);
        sy  += __shfl_xor_sync(0xFFFFFFFFu, sy,  o);
        sxx += __shfl_xor_sync(0xFFFFFFFFu, sxx, o);
        syy += __shfl_xor_sync(0xFFFFFFFFu, syy, o);
    }

    const float inv_n  = 1.0f / 64.0f;
    const float inv_nm1 = 1.0f / 63.0f;
    const float mx = sx * inv_n;
    const float my = sy * inv_n;
    // ddof=1 variance
    const float vx = fmaxf((sxx - 64.0f * mx * mx) * inv_nm1, 0.0f);
    const float vy = fmaxf((syy - 64.0f * my * my) * inv_nm1, 0.0f);
    const float rsx = 1.0f / (sqrtf(vx) + EPS);
    const float rsy = 1.0f / (sqrtf(vy) + EPS);

    // ---- Pass 2: sum of squared normalized differences ----
    const float d0 = (xv.x - mx) * rsx - (yv.x - my) * rsy;
    const float d1 = (xv.y - mx) * rsx - (yv.y - my) * rsy;
    float ss = d0 * d0 + d1 * d1;
    ss = warp_sum(ss);

    // ---- Quantum term: prod_{i<8} cos(x_i - y_i), squared ----
    // Lanes 0..3 hold columns 0..7 (2 per lane).
    float q = 1.0f;
    if (lane < 4)
        q = __cosf(xv.x - yv.x) * __cosf(xv.y - yv.y);
    // butterfly product within the 4-lane group {0,1,2,3}
    q *= __shfl_xor_sync(0xFFFFFFFFu, q, 1);
    q *= __shfl_xor_sync(0xFFFFFFFFu, q, 2);

    if (lane == 0)
        out[row] = __expf(-ss) + q * q;
}

extern "C" void kernel_launch(void* const* d_in, const int* in_sizes, int n_in,
                              void* d_out, int out_size)
{
    const float* x = (const float*)d_in[0];
    const float* y = (const float*)d_in[1];
    float* out = (float*)d_out;
    const int B = in_sizes[0] / 64;

    const int threads = 256;                 // 8 warps -> 8 rows per block
    const int blocks  = (B * 32 + threads - 1) / threads;
    hybrid_rbf_kernel<<<blocks, threads>>>(x, y, out, B);
}

// round 2
// speedup vs baseline: 2.2888x; 2.2888x over previous
#include <cuda_runtime.h>
#include <math.h>

#define EPS 1e-8f

// One warp processes 8 rows; 4 lanes per row; each lane owns 16 contiguous
// columns (4 x float4). Single fused pass computes 5 moments; segmented
// width-4 butterfly reduces them in 2 shuffle steps.
__global__ void __launch_bounds__(256) hybrid_rbf_kernel(
    const float* __restrict__ x,
    const float* __restrict__ y,
    float* __restrict__ out,
    int B)
{
    const int warp_id = (blockIdx.x * blockDim.x + threadIdx.x) >> 5;
    const int lane    = threadIdx.x & 31;
    const int group   = lane >> 2;   // 0..7 : which row within the warp
    const int j       = lane & 3;    // 0..3 : 16-column slice within the row
    const int row     = warp_id * 8 + group;
    if (row >= B) return;

    const float4* __restrict__ xr = reinterpret_cast<const float4*>(x + (size_t)row * 64) + j * 4;
    const float4* __restrict__ yr = reinterpret_cast<const float4*>(y + (size_t)row * 64) + j * 4;

    // Issue all loads up front (MLP = 8)
    float4 xv0 = xr[0], xv1 = xr[1], xv2 = xr[2], xv3 = xr[3];
    float4 yv0 = yr[0], yv1 = yr[1], yv2 = yr[2], yv3 = yr[3];

    // Fused single-pass moments: Sx, Sxx, Sy, Syy, Sxy
    float sx = 0.f, sxx = 0.f, sy = 0.f, syy = 0.f, sxy = 0.f;
    {
        const float4 xs[4] = {xv0, xv1, xv2, xv3};
        const float4 ys[4] = {yv0, yv1, yv2, yv3};
        #pragma unroll
        for (int k = 0; k < 4; k++) {
            const float xa[4] = {xs[k].x, xs[k].y, xs[k].z, xs[k].w};
            const float ya[4] = {ys[k].x, ys[k].y, ys[k].z, ys[k].w};
            #pragma unroll
            for (int e = 0; e < 4; e++) {
                const float xv = xa[e], yv = ya[e];
                sx  += xv;
                sy  += yv;
                sxx = fmaf(xv, xv, sxx);
                syy = fmaf(yv, yv, syy);
                sxy = fmaf(xv, yv, sxy);
            }
        }
    }

    // Segmented butterfly reduction over the 4-lane group (aligned, so xor 1,2 stay in-group)
    #pragma unroll
    for (int o = 1; o <= 2; o <<= 1) {
        sx  += __shfl_xor_sync(0xFFFFFFFFu, sx,  o);
        sy  += __shfl_xor_sync(0xFFFFFFFFu, sy,  o);
        sxx += __shfl_xor_sync(0xFFFFFFFFu, sxx, o);
        syy += __shfl_xor_sync(0xFFFFFFFFu, syy, o);
        sxy += __shfl_xor_sync(0xFFFFFFFFu, sxy, o);
    }

    if (j == 0) {
        const float inv_n   = 1.0f / 64.0f;
        const float inv_nm1 = 1.0f / 63.0f;
        const float mx = sx * inv_n;
        const float my = sy * inv_n;
        const float vx = fmaxf((sxx - 64.0f * mx * mx) * inv_nm1, 0.0f);
        const float vy = fmaxf((syy - 64.0f * my * my) * inv_nm1, 0.0f);
        const float fx = 1.0f / (sqrtf(vx) + EPS);
        const float fy = 1.0f / (sqrtf(vy) + EPS);
        const float cov = sxy - 64.0f * mx * my;     // sum (x-mx)(y-my)
        // sum (xhat - yhat)^2 = 63*vx*fx^2 + 63*vy*fy^2 - 2*cov*fx*fy
        const float ss = 63.0f * vx * fx * fx
                       + 63.0f * vy * fy * fy
                       - 2.0f * cov * fx * fy;

        // Quantum term: prod_{i<8} cos(x_i - y_i), squared. Lane j==0 holds raw cols 0..7.
        float q = __cosf(xv0.x - yv0.x) * __cosf(xv0.y - yv0.y)
                * __cosf(xv0.z - yv0.z) * __cosf(xv0.w - yv0.w);
        q      *= __cosf(xv1.x - yv1.x) * __cosf(xv1.y - yv1.y)
                * __cosf(xv1.z - yv1.z) * __cosf(xv1.w - yv1.w);

        out[row] = __expf(-ss) + q * q;
    }
}

extern "C" void kernel_launch(void* const* d_in, const int* in_sizes, int n_in,
                              void* d_out, int out_size)
{
    const float* x = (const float*)d_in[0];
    const float* y = (const float*)d_in[1];
    float* out = (float*)d_out;
    const int B = in_sizes[0] / 64;

    const int threads = 256;                    // 8 warps -> 64 rows per block
    const int rows_per_block = (threads / 32) * 8;
    const int blocks = (B + rows_per_block - 1) / rows_per_block;
    hybrid_rbf_kernel<<<blocks, threads>>>(x, y, out, B);
}